// round 4
// baseline (speedup 1.0000x reference)
#include <cuda_runtime.h>
#include <math.h>

// Problem constants (from setup_inputs): B=2, N=256, P=32, M=16, C=128, H=256
#define BD     2
#define NPTS   8192            // N*P
#define MM     16
#define CC     128
#define HH     256
#define ITEMS  (BD * NPTS * MM)   // 262144
#define TILE   64
#define NBLK   (ITEMS / TILE)     // 4096
#define KT     16                 // k-tile depth

// Precomputed per-(b,m) data
__device__ float g_cond[BD * MM * HH];  // psf @ Wc + bc
__device__ float g_R[BD * MM * 9];      // rotation matrices

// ---------------------------------------------------------------------------
// Prologue: cond = psf @ Wc + bc, and quaternion -> rotation matrix
// grid = BD*MM blocks, 256 threads
// ---------------------------------------------------------------------------
__global__ void precompute_kernel(const float* __restrict__ rotations,
                                  const float* __restrict__ psf,
                                  const float* __restrict__ Wc,
                                  const float* __restrict__ bc)
{
    __shared__ float s_psf[CC];
    const int bm = blockIdx.x;
    const int t  = threadIdx.x;

    if (t < CC) s_psf[t] = psf[bm * CC + t];
    __syncthreads();

    float acc = bc[t];
#pragma unroll 8
    for (int k = 0; k < CC; ++k)
        acc = fmaf(s_psf[k], Wc[k * HH + t], acc);
    g_cond[bm * HH + t] = acc;

    if (t == 0) {
        float w = rotations[bm * 4 + 0];
        float x = rotations[bm * 4 + 1];
        float y = rotations[bm * 4 + 2];
        float z = rotations[bm * 4 + 3];
        float inv = rsqrtf(w * w + x * x + y * y + z * z);
        w *= inv; x *= inv; y *= inv; z *= inv;
        float* R = g_R + bm * 9;
        R[0] = 1.f - 2.f * (y * y + z * z);
        R[1] = 2.f * (x * y - w * z);
        R[2] = 2.f * (x * z + w * y);
        R[3] = 2.f * (x * y + w * z);
        R[4] = 1.f - 2.f * (x * x + z * z);
        R[5] = 2.f * (y * z - w * x);
        R[6] = 2.f * (x * z - w * y);
        R[7] = 2.f * (y * z + w * x);
        R[8] = 1.f - 2.f * (x * x + y * y);
    }
}

// ---------------------------------------------------------------------------
// Tiled GEMM helper: acc[8][8] += (RELU_A ? relu(sA) : sA) @ W
// sA: TILE x HH in smem. W: HH x HH in gmem (streamed via sWt k-tiles).
// ---------------------------------------------------------------------------
template <bool RELU_A>
__device__ __forceinline__ void gemm_tile(const float* __restrict__ W,
                                          const float* sA, float* sWt,
                                          int t, int tx, int rb,
                                          float acc[8][8])
{
    for (int kt = 0; kt < HH / KT; ++kt) {
        __syncthreads();   // previous consumers done with sWt / producers of sA done
        {
            const float4* src = (const float4*)(W + kt * KT * HH);
            float4*       dst = (float4*)sWt;
#pragma unroll
            for (int u = 0; u < 4; ++u)
                dst[t + u * 256] = src[t + u * 256];
        }
        __syncthreads();
#pragma unroll
        for (int k = 0; k < KT; ++k) {
            float a[8];
#pragma unroll
            for (int ii = 0; ii < 8; ++ii) {
                float v = sA[(rb + ii) * HH + kt * KT + k];
                a[ii] = RELU_A ? fmaxf(v, 0.f) : v;
            }
            const float4* w4 = (const float4*)(sWt + k * HH);
            float4 wA = w4[tx * 2];
            float4 wB = w4[tx * 2 + 1];
            float wv[8] = {wA.x, wA.y, wA.z, wA.w, wB.x, wB.y, wB.z, wB.w};
#pragma unroll
            for (int ii = 0; ii < 8; ++ii)
#pragma unroll
                for (int jj = 0; jj < 8; ++jj)
                    acc[ii][jj] = fmaf(a[ii], wv[jj], acc[ii][jj]);
        }
    }
}

// ---------------------------------------------------------------------------
// Main fused kernel. 256 threads, 64 items per block.
// smem carve: A0(64x256) | A1(64x256) | Wt(16x256) | Wp(3x256) | bp(256)
//             | Xt(64x3) | Fell(64) | M(64)
// ---------------------------------------------------------------------------
#define SMEM_BYTES ((TILE*HH + TILE*HH + KT*HH + 3*HH + HH + TILE*3 + TILE + TILE) * 4)

__global__ void __launch_bounds__(256, 1)
occ_kernel(const float* __restrict__ ray_points,
           const float* __restrict__ translations,
           const float* __restrict__ scale,
           const float* __restrict__ Wp, const float* __restrict__ bp,
           const float* __restrict__ W1, const float* __restrict__ b1,
           const float* __restrict__ W2, const float* __restrict__ b2,
           const float* __restrict__ Wout, const float* __restrict__ bout,
           float* __restrict__ out)
{
    extern __shared__ float smem[];
    float* sA0   = smem;                   // 64*256
    float* sA1   = sA0 + TILE * HH;        // 64*256
    float* sWt   = sA1 + TILE * HH;        // 16*256 (also cond staging)
    float* sWp   = sWt + KT * HH;          // 3*256
    float* sbp   = sWp + 3 * HH;           // 256
    float* sXt   = sbp + HH;               // 64*3
    float* sFell = sXt + TILE * 3;         // 64
    int*   sM    = (int*)(sFell + TILE);   // 64

    const int t  = threadIdx.x;
    const int tx = t & 31;
    const int ty = t >> 5;
    const int rb = ty * 8;
    const int cb = tx * 8;

    const int item0 = blockIdx.x * TILE;
    const int b     = item0 >> 17;         // NPTS*MM = 131072 = 2^17

    // Load Wp, bp
    sWp[t]       = Wp[t];
    sWp[256 + t] = Wp[256 + t];
    sWp[512 + t] = Wp[512 + t];
    sbp[t]       = bp[t];

    // Stage cond rows for this b (16 x 256, contiguous) into sWt
    {
        const float4* src = (const float4*)(g_cond + b * MM * HH);
        float4*       dst = (float4*)sWt;
#pragma unroll
        for (int u = 0; u < 4; ++u)
            dst[t + u * 256] = src[t + u * 256];
    }

    // Phase 0a: geometry for 64 items
    if (t < TILE) {
        const int item = item0 + t;
        const int rem  = item & (NPTS * MM - 1);
        const int np_  = rem >> 4;
        const int m    = rem & 15;
        const int bm   = b * MM + m;

        const float px = ray_points[(b * NPTS + np_) * 3 + 0];
        const float py = ray_points[(b * NPTS + np_) * 3 + 1];
        const float pz = ray_points[(b * NPTS + np_) * 3 + 2];
        const float cx = px - translations[bm * 3 + 0];
        const float cy = py - translations[bm * 3 + 1];
        const float cz = pz - translations[bm * 3 + 2];
        const float* R = g_R + bm * 9;
        const float x0 = R[0] * cx + R[1] * cy + R[2] * cz;
        const float x1 = R[3] * cx + R[4] * cy + R[5] * cz;
        const float x2 = R[6] * cx + R[7] * cy + R[8] * cz;
        const float s0 = scale[bm * 3 + 0];
        const float s1 = scale[bm * 3 + 1];
        const float s2 = scale[bm * 3 + 2];
        const float q0 = x0 / s0, q1 = x1 / s1, q2 = x2 / s2;

        sXt[t * 3 + 0] = x0;
        sXt[t * 3 + 1] = x1;
        sXt[t * 3 + 2] = x2;
        sFell[t] = q0 * q0 + q1 * q1 + q2 * q2;
        sM[t]    = m;
    }
    __syncthreads();

    // Phase 0b: net0 = Xt @ Wp + bp + cond   -> sA0 (pre-relu, kept for residual)
    {
        const float wp0 = sWp[t], wp1 = sWp[256 + t], wp2 = sWp[512 + t];
        const float bb  = sbp[t];
        for (int i = 0; i < TILE; ++i) {
            float v = fmaf(sXt[i * 3 + 0], wp0,
                      fmaf(sXt[i * 3 + 1], wp1,
                      fmaf(sXt[i * 3 + 2], wp2, bb + sWt[sM[i] * HH + t])));
            sA0[i * HH + t] = v;
        }
    }
    // (gemm_tile's leading __syncthreads orders sA0/sWt usage)

    // GEMM1: h1 = relu(net0) @ W1
    float acc[8][8] = {};
    gemm_tile<true>(W1, sA0, sWt, t, tx, rb, acc);

    // Epilogue1: A1 = relu(h1 + b1)
    {
        float b1v[8];
#pragma unroll
        for (int jj = 0; jj < 8; ++jj) b1v[jj] = b1[cb + jj];
#pragma unroll
        for (int ii = 0; ii < 8; ++ii) {
            float4 v0, v1;
            v0.x = fmaxf(acc[ii][0] + b1v[0], 0.f);
            v0.y = fmaxf(acc[ii][1] + b1v[1], 0.f);
            v0.z = fmaxf(acc[ii][2] + b1v[2], 0.f);
            v0.w = fmaxf(acc[ii][3] + b1v[3], 0.f);
            v1.x = fmaxf(acc[ii][4] + b1v[4], 0.f);
            v1.y = fmaxf(acc[ii][5] + b1v[5], 0.f);
            v1.z = fmaxf(acc[ii][6] + b1v[6], 0.f);
            v1.w = fmaxf(acc[ii][7] + b1v[7], 0.f);
            float4* dst = (float4*)(sA1 + (rb + ii) * HH + cb);
            dst[0] = v0;
            dst[1] = v1;
        }
    }

    // GEMM2: dx_pre = relu(h1) @ W2
    float acc2[8][8] = {};
    gemm_tile<false>(W2, sA1, sWt, t, tx, rb, acc2);

    // Epilogue2: net = net0 + dx_pre + b2; occ = relu(net)@Wout + bout;
    //            F = mask ? occ : -100; out = sigmoid(10*F)
    {
        float b2v[8], wo[8];
#pragma unroll
        for (int jj = 0; jj < 8; ++jj) {
            b2v[jj] = b2[cb + jj];
            wo[jj]  = Wout[cb + jj];
        }
        const float bo = bout[0];
#pragma unroll
        for (int ii = 0; ii < 8; ++ii) {
            float p = 0.f;
#pragma unroll
            for (int jj = 0; jj < 8; ++jj) {
                float net = sA0[(rb + ii) * HH + cb + jj] + acc2[ii][jj] + b2v[jj];
                p = fmaf(fmaxf(net, 0.f), wo[jj], p);
            }
#pragma unroll
            for (int off = 16; off > 0; off >>= 1)
                p += __shfl_xor_sync(0xffffffffu, p, off);
            if (tx == 0) {
                const int r = rb + ii;
                const float occ = p + bo;
                const float F   = (sFell[r] <= 1.0f) ? occ : -100.0f;
                out[item0 + r]  = 1.0f / (1.0f + expf(-10.0f * F));
            }
        }
    }
}

// ---------------------------------------------------------------------------
// Launch
// ---------------------------------------------------------------------------
extern "C" void kernel_launch(void* const* d_in, const int* in_sizes, int n_in,
                              void* d_out, int out_size)
{
    const float* ray_points   = (const float*)d_in[0];
    const float* translations = (const float*)d_in[1];
    const float* rotations    = (const float*)d_in[2];
    const float* scale        = (const float*)d_in[3];
    const float* psf          = (const float*)d_in[4];
    const float* Wp           = (const float*)d_in[5];
    const float* bp           = (const float*)d_in[6];
    const float* Wc           = (const float*)d_in[7];
    const float* bc           = (const float*)d_in[8];
    const float* W1           = (const float*)d_in[9];
    const float* b1           = (const float*)d_in[10];
    const float* W2           = (const float*)d_in[11];
    const float* b2           = (const float*)d_in[12];
    const float* Wout         = (const float*)d_in[13];
    const float* bout         = (const float*)d_in[14];
    float*       out          = (float*)d_out;

    cudaFuncSetAttribute(occ_kernel,
                         cudaFuncAttributeMaxDynamicSharedMemorySize,
                         SMEM_BYTES);

    precompute_kernel<<<BD * MM, 256>>>(rotations, psf, Wc, bc);
    occ_kernel<<<NBLK, 256, SMEM_BYTES>>>(ray_points, translations, scale,
                                          Wp, bp, W1, b1, W2, b2, Wout, bout,
                                          out);
}

// round 5
// speedup vs baseline: 1.0003x; 1.0003x over previous
#include <cuda_runtime.h>
#include <math.h>

// Problem constants (from setup_inputs): B=2, N=256, P=32, M=16, C=128, H=256
#define BD     2
#define NPTS   8192            // N*P
#define MM     16
#define CC     128
#define HH     256
#define ITEMS  (BD * NPTS * MM)   // 262144
#define TILE   64
#define NBLK   (ITEMS / TILE)     // 4096
#define KT     16                 // k-tile depth

// Precomputed per-(b,m) data
__device__ float g_cond[BD * MM * HH];  // psf @ Wc + bc
__device__ float g_R[BD * MM * 9];      // rotation matrices

// ---------------------------------------------------------------------------
// Prologue: cond = psf @ Wc + bc, and quaternion -> rotation matrix
// grid = BD*MM blocks, 256 threads
// ---------------------------------------------------------------------------
__global__ void precompute_kernel(const float* __restrict__ rotations,
                                  const float* __restrict__ psf,
                                  const float* __restrict__ Wc,
                                  const float* __restrict__ bc)
{
    __shared__ float s_psf[CC];
    const int bm = blockIdx.x;
    const int t  = threadIdx.x;

    if (t < CC) s_psf[t] = psf[bm * CC + t];
    __syncthreads();

    float acc = bc[t];
#pragma unroll 8
    for (int k = 0; k < CC; ++k)
        acc = fmaf(s_psf[k], Wc[k * HH + t], acc);
    g_cond[bm * HH + t] = acc;

    if (t == 0) {
        float w = rotations[bm * 4 + 0];
        float x = rotations[bm * 4 + 1];
        float y = rotations[bm * 4 + 2];
        float z = rotations[bm * 4 + 3];
        float inv = rsqrtf(w * w + x * x + y * y + z * z);
        w *= inv; x *= inv; y *= inv; z *= inv;
        float* R = g_R + bm * 9;
        R[0] = 1.f - 2.f * (y * y + z * z);
        R[1] = 2.f * (x * y - w * z);
        R[2] = 2.f * (x * z + w * y);
        R[3] = 2.f * (x * y + w * z);
        R[4] = 1.f - 2.f * (x * x + z * z);
        R[5] = 2.f * (y * z - w * x);
        R[6] = 2.f * (x * z - w * y);
        R[7] = 2.f * (y * z + w * x);
        R[8] = 1.f - 2.f * (x * x + y * y);
    }
}

// ---------------------------------------------------------------------------
// Tiled GEMM helper: acc[8][8] += (RELU_A ? relu(sA) : sA) @ W
// sA: TILE x HH in smem. W: HH x HH in gmem (streamed via sWt k-tiles).
// ---------------------------------------------------------------------------
template <bool RELU_A>
__device__ __forceinline__ void gemm_tile(const float* __restrict__ W,
                                          const float* sA, float* sWt,
                                          int t, int tx, int rb,
                                          float acc[8][8])
{
    for (int kt = 0; kt < HH / KT; ++kt) {
        __syncthreads();   // previous consumers done with sWt / producers of sA done
        {
            const float4* src = (const float4*)(W + kt * KT * HH);
            float4*       dst = (float4*)sWt;
#pragma unroll
            for (int u = 0; u < 4; ++u)
                dst[t + u * 256] = src[t + u * 256];
        }
        __syncthreads();
#pragma unroll
        for (int k = 0; k < KT; ++k) {
            float a[8];
#pragma unroll
            for (int ii = 0; ii < 8; ++ii) {
                float v = sA[(rb + ii) * HH + kt * KT + k];
                a[ii] = RELU_A ? fmaxf(v, 0.f) : v;
            }
            const float4* w4 = (const float4*)(sWt + k * HH);
            float4 wA = w4[tx * 2];
            float4 wB = w4[tx * 2 + 1];
            float wv[8] = {wA.x, wA.y, wA.z, wA.w, wB.x, wB.y, wB.z, wB.w};
#pragma unroll
            for (int ii = 0; ii < 8; ++ii)
#pragma unroll
                for (int jj = 0; jj < 8; ++jj)
                    acc[ii][jj] = fmaf(a[ii], wv[jj], acc[ii][jj]);
        }
    }
}

// ---------------------------------------------------------------------------
// Main fused kernel. 256 threads, 64 items per block.
// smem carve: A0(64x256) | A1(64x256) | Wt(16x256) | Wp(3x256) | bp(256)
//             | Xt(64x3) | Fell(64) | M(64)
// ---------------------------------------------------------------------------
#define SMEM_BYTES ((TILE*HH + TILE*HH + KT*HH + 3*HH + HH + TILE*3 + TILE + TILE) * 4)

__global__ void __launch_bounds__(256, 1)
occ_kernel(const float* __restrict__ ray_points,
           const float* __restrict__ translations,
           const float* __restrict__ scale,
           const float* __restrict__ Wp, const float* __restrict__ bp,
           const float* __restrict__ W1, const float* __restrict__ b1,
           const float* __restrict__ W2, const float* __restrict__ b2,
           const float* __restrict__ Wout, const float* __restrict__ bout,
           float* __restrict__ out)
{
    extern __shared__ float smem[];
    float* sA0   = smem;                   // 64*256
    float* sA1   = sA0 + TILE * HH;        // 64*256
    float* sWt   = sA1 + TILE * HH;        // 16*256 (also cond staging)
    float* sWp   = sWt + KT * HH;          // 3*256
    float* sbp   = sWp + 3 * HH;           // 256
    float* sXt   = sbp + HH;               // 64*3
    float* sFell = sXt + TILE * 3;         // 64
    int*   sM    = (int*)(sFell + TILE);   // 64

    const int t  = threadIdx.x;
    const int tx = t & 31;
    const int ty = t >> 5;
    const int rb = ty * 8;
    const int cb = tx * 8;

    const int item0 = blockIdx.x * TILE;
    const int b     = item0 >> 17;         // NPTS*MM = 131072 = 2^17

    // Load Wp, bp
    sWp[t]       = Wp[t];
    sWp[256 + t] = Wp[256 + t];
    sWp[512 + t] = Wp[512 + t];
    sbp[t]       = bp[t];

    // Stage cond rows for this b (16 x 256, contiguous) into sWt
    {
        const float4* src = (const float4*)(g_cond + b * MM * HH);
        float4*       dst = (float4*)sWt;
#pragma unroll
        for (int u = 0; u < 4; ++u)
            dst[t + u * 256] = src[t + u * 256];
    }

    // Phase 0a: geometry for 64 items
    if (t < TILE) {
        const int item = item0 + t;
        const int rem  = item & (NPTS * MM - 1);
        const int np_  = rem >> 4;
        const int m    = rem & 15;
        const int bm   = b * MM + m;

        const float px = ray_points[(b * NPTS + np_) * 3 + 0];
        const float py = ray_points[(b * NPTS + np_) * 3 + 1];
        const float pz = ray_points[(b * NPTS + np_) * 3 + 2];
        const float cx = px - translations[bm * 3 + 0];
        const float cy = py - translations[bm * 3 + 1];
        const float cz = pz - translations[bm * 3 + 2];
        const float* R = g_R + bm * 9;
        const float x0 = R[0] * cx + R[1] * cy + R[2] * cz;
        const float x1 = R[3] * cx + R[4] * cy + R[5] * cz;
        const float x2 = R[6] * cx + R[7] * cy + R[8] * cz;
        const float s0 = scale[bm * 3 + 0];
        const float s1 = scale[bm * 3 + 1];
        const float s2 = scale[bm * 3 + 2];
        const float q0 = x0 / s0, q1 = x1 / s1, q2 = x2 / s2;

        sXt[t * 3 + 0] = x0;
        sXt[t * 3 + 1] = x1;
        sXt[t * 3 + 2] = x2;
        sFell[t] = q0 * q0 + q1 * q1 + q2 * q2;
        sM[t]    = m;
    }
    __syncthreads();

    // Phase 0b: net0 = Xt @ Wp + bp + cond   -> sA0 (pre-relu, kept for residual)
    {
        const float wp0 = sWp[t], wp1 = sWp[256 + t], wp2 = sWp[512 + t];
        const float bb  = sbp[t];
        for (int i = 0; i < TILE; ++i) {
            float v = fmaf(sXt[i * 3 + 0], wp0,
                      fmaf(sXt[i * 3 + 1], wp1,
                      fmaf(sXt[i * 3 + 2], wp2, bb + sWt[sM[i] * HH + t])));
            sA0[i * HH + t] = v;
        }
    }
    // (gemm_tile's leading __syncthreads orders sA0/sWt usage)

    // GEMM1: h1 = relu(net0) @ W1
    float acc[8][8] = {};
    gemm_tile<true>(W1, sA0, sWt, t, tx, rb, acc);

    // Epilogue1: A1 = relu(h1 + b1)
    {
        float b1v[8];
#pragma unroll
        for (int jj = 0; jj < 8; ++jj) b1v[jj] = b1[cb + jj];
#pragma unroll
        for (int ii = 0; ii < 8; ++ii) {
            float4 v0, v1;
            v0.x = fmaxf(acc[ii][0] + b1v[0], 0.f);
            v0.y = fmaxf(acc[ii][1] + b1v[1], 0.f);
            v0.z = fmaxf(acc[ii][2] + b1v[2], 0.f);
            v0.w = fmaxf(acc[ii][3] + b1v[3], 0.f);
            v1.x = fmaxf(acc[ii][4] + b1v[4], 0.f);
            v1.y = fmaxf(acc[ii][5] + b1v[5], 0.f);
            v1.z = fmaxf(acc[ii][6] + b1v[6], 0.f);
            v1.w = fmaxf(acc[ii][7] + b1v[7], 0.f);
            float4* dst = (float4*)(sA1 + (rb + ii) * HH + cb);
            dst[0] = v0;
            dst[1] = v1;
        }
    }

    // GEMM2: dx_pre = relu(h1) @ W2
    float acc2[8][8] = {};
    gemm_tile<false>(W2, sA1, sWt, t, tx, rb, acc2);

    // Epilogue2: net = net0 + dx_pre + b2; occ = relu(net)@Wout + bout;
    //            F = mask ? occ : -100; out = sigmoid(10*F)
    {
        float b2v[8], wo[8];
#pragma unroll
        for (int jj = 0; jj < 8; ++jj) {
            b2v[jj] = b2[cb + jj];
            wo[jj]  = Wout[cb + jj];
        }
        const float bo = bout[0];
#pragma unroll
        for (int ii = 0; ii < 8; ++ii) {
            float p = 0.f;
#pragma unroll
            for (int jj = 0; jj < 8; ++jj) {
                float net = sA0[(rb + ii) * HH + cb + jj] + acc2[ii][jj] + b2v[jj];
                p = fmaf(fmaxf(net, 0.f), wo[jj], p);
            }
#pragma unroll
            for (int off = 16; off > 0; off >>= 1)
                p += __shfl_xor_sync(0xffffffffu, p, off);
            if (tx == 0) {
                const int r = rb + ii;
                const float occ = p + bo;
                const float F   = (sFell[r] <= 1.0f) ? occ : -100.0f;
                out[item0 + r]  = 1.0f / (1.0f + expf(-10.0f * F));
            }
        }
    }
}

// ---------------------------------------------------------------------------
// Launch
// ---------------------------------------------------------------------------
extern "C" void kernel_launch(void* const* d_in, const int* in_sizes, int n_in,
                              void* d_out, int out_size)
{
    const float* ray_points   = (const float*)d_in[0];
    const float* translations = (const float*)d_in[1];
    const float* rotations    = (const float*)d_in[2];
    const float* scale        = (const float*)d_in[3];
    const float* psf          = (const float*)d_in[4];
    const float* Wp           = (const float*)d_in[5];
    const float* bp           = (const float*)d_in[6];
    const float* Wc           = (const float*)d_in[7];
    const float* bc           = (const float*)d_in[8];
    const float* W1           = (const float*)d_in[9];
    const float* b1           = (const float*)d_in[10];
    const float* W2           = (const float*)d_in[11];
    const float* b2           = (const float*)d_in[12];
    const float* Wout         = (const float*)d_in[13];
    const float* bout         = (const float*)d_in[14];
    float*       out          = (float*)d_out;

    cudaFuncSetAttribute(occ_kernel,
                         cudaFuncAttributeMaxDynamicSharedMemorySize,
                         SMEM_BYTES);

    precompute_kernel<<<BD * MM, 256>>>(rotations, psf, Wc, bc);
    occ_kernel<<<NBLK, 256, SMEM_BYTES>>>(ray_points, translations, scale,
                                          Wp, bp, W1, b1, W2, b2, Wout, bout,
                                          out);
}

// round 8
// speedup vs baseline: 1.6926x; 1.6920x over previous
#include <cuda_runtime.h>
#include <cuda_bf16.h>
#include <math.h>
#include <stdint.h>

#define BD 2
#define NPTS 8192
#define MM 16
#define HH 256
#define CC 128
#define ITEMS (BD*NPTS*MM)
#define TILE 128
#define NBLK (ITEMS/TILE)       // 2048
#define LDA 264                  // A smem row stride (elements)
#define LDB 40                   // W chunk row stride (elements)

// smem offsets (bytes)
#define A_HI_OFF 0
#define A_LO_OFF 67584
#define WBUF_OFF 135168          // 2 buffers x 40960 (each: hi 20480 + lo 20480)
#define WP_OFF   217088
#define BP_OFF   220160
#define B1_OFF   221184
#define B2_OFF   222208
#define WO_OFF   223232
#define XT_OFF   224256
#define FELL_OFF 225792
#define MI_OFF   226304
#define SP_OFF   226816
#define SMEM_BYTES 228864

__device__ float g_cond[BD*MM*HH];   // [bm][j]
__device__ float g_R[BD*MM*9];
// Wt bf16: [layer][part(hi/lo)][n][k], k contiguous. layer stride 262144B, part 131072B, row 512B
__device__ __align__(16) unsigned char g_Wb[2*2*256*256*2];

// ---------------- PTX helpers ----------------
__device__ __forceinline__ uint32_t smem_u32(const void* p){
    uint32_t a;
    asm("{ .reg .u64 t; cvta.to.shared.u64 t, %1; cvt.u32.u64 %0, t; }":"=r"(a):"l"(p));
    return a;
}
__device__ __forceinline__ void ldsm4(uint32_t* r, uint32_t addr){
    asm volatile("ldmatrix.sync.aligned.m8n8.x4.shared.b16 {%0,%1,%2,%3}, [%4];"
        : "=r"(r[0]),"=r"(r[1]),"=r"(r[2]),"=r"(r[3]) : "r"(addr));
}
__device__ __forceinline__ void mma16816(float* d, const uint32_t* a, uint32_t b0, uint32_t b1){
    asm volatile("mma.sync.aligned.m16n8k16.row.col.f32.bf16.bf16.f32 "
        "{%0,%1,%2,%3}, {%4,%5,%6,%7}, {%8,%9}, {%0,%1,%2,%3};"
        : "+f"(d[0]),"+f"(d[1]),"+f"(d[2]),"+f"(d[3])
        : "r"(a[0]),"r"(a[1]),"r"(a[2]),"r"(a[3]), "r"(b0),"r"(b1));
}
__device__ __forceinline__ void split_pack(float v0, float v1, uint32_t& hi, uint32_t& lo){
    __nv_bfloat16 h0=__float2bfloat16_rn(v0), h1=__float2bfloat16_rn(v1);
    __nv_bfloat16 l0=__float2bfloat16_rn(v0-__bfloat162float(h0));
    __nv_bfloat16 l1=__float2bfloat16_rn(v1-__bfloat162float(h1));
    __nv_bfloat162 hp; hp.x=h0; hp.y=h1;
    __nv_bfloat162 lp; lp.x=l0; lp.y=l1;
    hi=*reinterpret_cast<uint32_t*>(&hp); lo=*reinterpret_cast<uint32_t*>(&lp);
}

// ---------------- prologues ----------------
__global__ void precompute_kernel(const float* __restrict__ rotations,
                                  const float* __restrict__ psf,
                                  const float* __restrict__ Wc,
                                  const float* __restrict__ bc)
{
    __shared__ float s_psf[CC];
    const int bm = blockIdx.x, t = threadIdx.x;
    if (t < CC) s_psf[t] = psf[bm*CC + t];
    __syncthreads();
    float acc = bc[t];
#pragma unroll 8
    for (int k = 0; k < CC; ++k) acc = fmaf(s_psf[k], Wc[k*HH + t], acc);
    g_cond[bm*HH + t] = acc;
    if (t == 0) {
        float w=rotations[bm*4],x=rotations[bm*4+1],y=rotations[bm*4+2],z=rotations[bm*4+3];
        float inv = rsqrtf(w*w+x*x+y*y+z*z);
        w*=inv; x*=inv; y*=inv; z*=inv;
        float* R = g_R + bm*9;
        R[0]=1.f-2.f*(y*y+z*z); R[1]=2.f*(x*y-w*z); R[2]=2.f*(x*z+w*y);
        R[3]=2.f*(x*y+w*z); R[4]=1.f-2.f*(x*x+z*z); R[5]=2.f*(y*z-w*x);
        R[6]=2.f*(x*z-w*y); R[7]=2.f*(y*z+w*x); R[8]=1.f-2.f*(x*x+y*y);
    }
}

__global__ void precompute_W_kernel(const float* __restrict__ W1,
                                    const float* __restrict__ W2)
{
    const int idx = blockIdx.x*256 + threadIdx.x;   // 0..131071
    const int layer = idx >> 16;
    const int e = idx & 65535;
    const int k = e >> 8, n = e & 255;
    const float v = (layer ? W2 : W1)[k*HH + n];
    __nv_bfloat16 hi = __float2bfloat16_rn(v);
    __nv_bfloat16 lo = __float2bfloat16_rn(v - __bfloat162float(hi));
    // Wt[layer][part][n][k]
    size_t o = ((size_t)(layer*2)*256 + n)*256 + k;
    *(__nv_bfloat16*)(g_Wb + o*2)            = hi;
    *(__nv_bfloat16*)(g_Wb + (o + 65536)*2)  = lo;   // part stride = 256*256 elems
}

// ---------------- main kernel ----------------
// prefetch one k-chunk (k0 = c*32): 2 parts x 256 rows x 64B
__device__ __forceinline__ void prefetch_chunk(uint32_t dst, int layer, int c, int t){
#pragma unroll
    for (int i = 0; i < 4; ++i) {
        const int idx = t*4 + i;                 // 0..2047
        const int p   = idx >> 10;
        const int n   = (idx >> 2) & 255;
        const int seg = idx & 3;
        const unsigned char* src = g_Wb + (size_t)layer*262144 + (size_t)p*131072
                                 + (size_t)n*512 + c*64 + seg*16;
        const uint32_t d = dst + p*20480 + n*(LDB*2) + seg*16;
        asm volatile("cp.async.cg.shared.global [%0], [%1], 16;" :: "r"(d), "l"(src));
    }
    asm volatile("cp.async.commit_group;" ::: "memory");
}

__device__ __forceinline__ void gemm_layer(int layer, int has_next,
    uint32_t sb, float acc[2][8][4], int t,
    int m0, int n0, int row_a, int k_a, int n_b, int k_b)
{
    for (int c = 0; c < 8; ++c) {
        if (c < 7)       prefetch_chunk(sb + WBUF_OFF + ((c+1)&1)*40960, layer,   c+1, t);
        else if (has_next) prefetch_chunk(sb + WBUF_OFF,                 layer+1, 0,   t);
        if (c < 7 || has_next) { asm volatile("cp.async.wait_group 1;" ::: "memory"); }
        else                   { asm volatile("cp.async.wait_group 0;" ::: "memory"); }
        __syncthreads();
        const uint32_t buf = sb + WBUF_OFF + (c&1)*40960;
#pragma unroll
        for (int ks = 0; ks < 2; ++ks) {
            const int kg = c*32 + ks*16;
            const int kl = ks*16;
            uint32_t ah[2][4], al[2][4];
#pragma unroll
            for (int mt = 0; mt < 2; ++mt) {
                const uint32_t ro = (uint32_t)((m0 + mt*16 + row_a)*LDA + kg + k_a)*2;
                ldsm4(ah[mt], sb + A_HI_OFF + ro);
                ldsm4(al[mt], sb + A_LO_OFF + ro);
            }
#pragma unroll
            for (int ntg = 0; ntg < 4; ++ntg) {
                uint32_t bh[4], bl[4];
                const uint32_t bo = buf + (uint32_t)((n0 + ntg*16 + n_b)*LDB + kl + k_b)*2;
                ldsm4(bh, bo);
                ldsm4(bl, bo + 20480);
#pragma unroll
                for (int mt = 0; mt < 2; ++mt) {
                    float* d0 = acc[mt][2*ntg];
                    float* d1 = acc[mt][2*ntg+1];
                    mma16816(d0, ah[mt], bh[0], bh[1]);
                    mma16816(d0, ah[mt], bl[0], bl[1]);
                    mma16816(d0, al[mt], bh[0], bh[1]);
                    mma16816(d1, ah[mt], bh[2], bh[3]);
                    mma16816(d1, ah[mt], bl[2], bl[3]);
                    mma16816(d1, al[mt], bh[2], bh[3]);
                }
            }
        }
        __syncthreads();
    }
}

__global__ void __launch_bounds__(512,1)
occ_mma_kernel(const float* __restrict__ ray_points,
               const float* __restrict__ translations,
               const float* __restrict__ scale,
               const float* __restrict__ Wp, const float* __restrict__ bp,
               const float* __restrict__ b1, const float* __restrict__ b2,
               const float* __restrict__ Wout, const float* __restrict__ bout,
               float* __restrict__ out)
{
    extern __shared__ __align__(16) unsigned char smem[];
    const uint32_t sb = smem_u32(smem);
    float* sWp  = (float*)(smem + WP_OFF);
    float* sbp  = (float*)(smem + BP_OFF);
    float* sb1  = (float*)(smem + B1_OFF);
    float* sb2  = (float*)(smem + B2_OFF);
    float* sWo  = (float*)(smem + WO_OFF);
    float* sXt  = (float*)(smem + XT_OFF);
    float* sFell= (float*)(smem + FELL_OFF);
    int*   sMi  = (int*)  (smem + MI_OFF);
    float* sP   = (float*)(smem + SP_OFF);

    const int t = threadIdx.x;
    const int w = t >> 5, l = t & 31;
    const int m0 = (w >> 2) * 32;
    const int ng = w & 3;
    const int n0 = ng * 64;
    const int li = l & 7, grp = l >> 3;
    // ldmatrix per-thread address components
    const int row_a = li + ((grp & 1) << 3);
    const int k_a   = (grp >> 1) << 3;
    const int n_b   = li + ((grp >> 1) << 3);
    const int k_b   = (grp & 1) << 3;

    const int item0 = blockIdx.x * TILE;
    const int b = item0 >> 17;

    prefetch_chunk(sb + WBUF_OFF, 0, 0, t);   // layer0 chunk0

    if (t < 256) {
        sWp[t]=Wp[t]; sWp[256+t]=Wp[256+t]; sWp[512+t]=Wp[512+t];
        sbp[t]=bp[t]; sb1[t]=b1[t]; sb2[t]=b2[t]; sWo[t]=Wout[t];
    }
    if (t < TILE) {
        const int item = item0 + t;
        const int rem = item & (NPTS*MM - 1);
        const int np_ = rem >> 4, m = rem & 15, bm = b*MM + m;
        const float px=ray_points[(b*NPTS+np_)*3], py=ray_points[(b*NPTS+np_)*3+1], pz=ray_points[(b*NPTS+np_)*3+2];
        const float cx=px-translations[bm*3], cy=py-translations[bm*3+1], cz=pz-translations[bm*3+2];
        const float* R = g_R + bm*9;
        const float x0=R[0]*cx+R[1]*cy+R[2]*cz;
        const float x1=R[3]*cx+R[4]*cy+R[5]*cz;
        const float x2=R[6]*cx+R[7]*cy+R[8]*cz;
        const float q0=x0/scale[bm*3], q1=x1/scale[bm*3+1], q2=x2/scale[bm*3+2];
        sXt[t*3]=x0; sXt[t*3+1]=x1; sXt[t*3+2]=x2;
        sFell[t]=q0*q0+q1*q1+q2*q2; sMi[t]=m;
    }
    __syncthreads();

    // Build A0 = relu(net0) as bf16 hi/lo. Thread t: row r=t>>2, cols (t&3)*64..+63
    {
        const int r = t >> 2, q = t & 3;
        const float x0=sXt[r*3], x1=sXt[r*3+1], x2=sXt[r*3+2];
        const int m = sMi[r];
        const float* cond = g_cond + (b*MM + m)*HH;
        uint32_t* dH = (uint32_t*)(smem + A_HI_OFF + (r*LDA + q*64)*2);
        uint32_t* dL = (uint32_t*)(smem + A_LO_OFF + (r*LDA + q*64)*2);
#pragma unroll 8
        for (int jj = 0; jj < 32; ++jj) {
            const int j = q*64 + 2*jj;
            float v0 = fmaf(x0,sWp[j],  fmaf(x1,sWp[256+j],  fmaf(x2,sWp[512+j],  sbp[j]  +cond[j])));
            float v1 = fmaf(x0,sWp[j+1],fmaf(x1,sWp[256+j+1],fmaf(x2,sWp[512+j+1],sbp[j+1]+cond[j+1])));
            uint32_t hi, lo;
            split_pack(fmaxf(v0,0.f), fmaxf(v1,0.f), hi, lo);
            dH[jj] = hi; dL[jj] = lo;
        }
    }
    __syncthreads();

    float acc[2][8][4];
#pragma unroll
    for (int a=0;a<2;++a)
#pragma unroll
        for (int c=0;c<8;++c)
#pragma unroll
            for (int k=0;k<4;++k) acc[a][c][k]=0.f;

    // ---- GEMM1 ----
    gemm_layer(0, 1, sb, acc, t, m0, n0, row_a, k_a, n_b, k_b);

    // Epilogue1 (in regs): A1 = relu(acc + b1) -> split -> back into A smem
#pragma unroll
    for (int mt = 0; mt < 2; ++mt) {
#pragma unroll
        for (int nt = 0; nt < 8; ++nt) {
            const int j0 = n0 + nt*8 + ((l&3)<<1);
            const int r0 = m0 + mt*16 + (l>>2);
            float v0 = fmaxf(acc[mt][nt][0] + sb1[j0],   0.f);
            float v1 = fmaxf(acc[mt][nt][1] + sb1[j0+1], 0.f);
            float v2 = fmaxf(acc[mt][nt][2] + sb1[j0],   0.f);
            float v3 = fmaxf(acc[mt][nt][3] + sb1[j0+1], 0.f);
            uint32_t hi, lo;
            split_pack(v0, v1, hi, lo);
            *(uint32_t*)(smem + A_HI_OFF + (r0*LDA + j0)*2) = hi;
            *(uint32_t*)(smem + A_LO_OFF + (r0*LDA + j0)*2) = lo;
            split_pack(v2, v3, hi, lo);
            *(uint32_t*)(smem + A_HI_OFF + ((r0+8)*LDA + j0)*2) = hi;
            *(uint32_t*)(smem + A_LO_OFF + ((r0+8)*LDA + j0)*2) = lo;
            acc[mt][nt][0]=0.f; acc[mt][nt][1]=0.f; acc[mt][nt][2]=0.f; acc[mt][nt][3]=0.f;
        }
    }
    __syncthreads();

    // ---- GEMM2 ----
    gemm_layer(1, 0, sb, acc, t, m0, n0, row_a, k_a, n_b, k_b);

    // Final epilogue: net = net0 + acc + b2; p = sum relu(net)*Wout
    {
        float X0[2][2], X1[2][2], X2[2][2];
        int   Mi[2][2];
#pragma unroll
        for (int mt = 0; mt < 2; ++mt)
#pragma unroll
            for (int h = 0; h < 2; ++h) {
                const int r = m0 + mt*16 + (l>>2) + h*8;
                X0[mt][h]=sXt[r*3]; X1[mt][h]=sXt[r*3+1]; X2[mt][h]=sXt[r*3+2];
                Mi[mt][h]=sMi[r];
            }
        float ps[2][2] = {{0.f,0.f},{0.f,0.f}};
#pragma unroll
        for (int mt = 0; mt < 2; ++mt) {
#pragma unroll
            for (int nt = 0; nt < 8; ++nt) {
                const int j0 = n0 + nt*8 + ((l&3)<<1);
#pragma unroll
                for (int k = 0; k < 4; ++k) {
                    const int j = j0 + (k & 1);
                    const int h = k >> 1;
                    const float cnd = g_cond[(b*MM + Mi[mt][h])*HH + j];
                    float net0 = fmaf(X0[mt][h],sWp[j],
                                 fmaf(X1[mt][h],sWp[256+j],
                                 fmaf(X2[mt][h],sWp[512+j], sbp[j] + cnd)));
                    float net = net0 + acc[mt][nt][k] + sb2[j];
                    ps[mt][h] = fmaf(fmaxf(net,0.f), sWo[j], ps[mt][h]);
                }
            }
        }
#pragma unroll
        for (int mt = 0; mt < 2; ++mt)
#pragma unroll
            for (int h = 0; h < 2; ++h) {
                float p = ps[mt][h];
                p += __shfl_xor_sync(0xffffffffu, p, 1);
                p += __shfl_xor_sync(0xffffffffu, p, 2);
                if ((l & 3) == 0) {
                    const int r = m0 + mt*16 + (l>>2) + h*8;
                    sP[r*4 + ng] = p;
                }
            }
    }
    __syncthreads();
    if (t < TILE) {
        const float occ = sP[t*4] + sP[t*4+1] + sP[t*4+2] + sP[t*4+3] + bout[0];
        const float F   = (sFell[t] <= 1.0f) ? occ : -100.0f;
        out[item0 + t]  = 1.0f / (1.0f + expf(-10.0f * F));
    }
}

// ---------------- launch ----------------
extern "C" void kernel_launch(void* const* d_in, const int* in_sizes, int n_in,
                              void* d_out, int out_size)
{
    const float* ray_points   = (const float*)d_in[0];
    const float* translations = (const float*)d_in[1];
    const float* rotations    = (const float*)d_in[2];
    const float* scale        = (const float*)d_in[3];
    const float* psf          = (const float*)d_in[4];
    const float* Wp   = (const float*)d_in[5];
    const float* bp   = (const float*)d_in[6];
    const float* Wc   = (const float*)d_in[7];
    const float* bc   = (const float*)d_in[8];
    const float* W1   = (const float*)d_in[9];
    const float* b1   = (const float*)d_in[10];
    const float* W2   = (const float*)d_in[11];
    const float* b2   = (const float*)d_in[12];
    const float* Wout = (const float*)d_in[13];
    const float* bout = (const float*)d_in[14];
    float*       out  = (float*)d_out;

    cudaFuncSetAttribute(occ_mma_kernel,
                         cudaFuncAttributeMaxDynamicSharedMemorySize, SMEM_BYTES);

    precompute_kernel<<<BD*MM, 256>>>(rotations, psf, Wc, bc);
    precompute_W_kernel<<<512, 256>>>(W1, W2);
    occ_mma_kernel<<<NBLK, 512, SMEM_BYTES>>>(ray_points, translations, scale,
                                              Wp, bp, b1, b2, Wout, bout, out);
}